// round 10
// baseline (speedup 1.0000x reference)
#include <cuda_runtime.h>
#include <cuda_fp16.h>
#include <mma.h>
#include <math.h>

using namespace nvcuda;

#define B_BATCH 2048
#define DMODEL  768
#define M_ROWS  (B_BATCH * 64)   // 131072

__device__ __half g_Hhi[(size_t)M_ROWS * DMODEL];
__device__ __half g_Hlo[(size_t)M_ROWS * DMODEL];
__device__ float  g_QK [(size_t)M_ROWS * 128];
__device__ __half g_W1T [DMODEL * DMODEL];
__device__ __half g_WqkT[128 * DMODEL];

// ---------------- helpers ----------------
__device__ __forceinline__ unsigned s2u(const void* p) {
    unsigned a;
    asm("{ .reg .u64 t; cvta.to.shared.u64 t, %1; cvt.u32.u64 %0, t; }" : "=r"(a) : "l"(p));
    return a;
}
__device__ __forceinline__ void cp16(unsigned dst, const void* src) {
    asm volatile("cp.async.cg.shared.global [%0], [%1], 16;" :: "r"(dst), "l"(src));
}
#define CP_COMMIT() asm volatile("cp.async.commit_group;" ::: "memory")
#define CP_WAIT0()  asm volatile("cp.async.wait_group 0;" ::: "memory")

__device__ __forceinline__ unsigned h2u(__half2 v) { return *reinterpret_cast<unsigned*>(&v); }

// exact fp32 -> fp16 hi+lo split for a pair
__device__ __forceinline__ void split2(float x, float y, unsigned& hi, unsigned& lo) {
    __half2 h = __floats2half2_rn(x, y);
    __half2 l = __floats2half2_rn(x - __low2float(h), y - __high2float(h));
    hi = h2u(h); lo = h2u(l);
}

// mish(x) = x*tanh(softplus(x)) = x*(t^2+2t)/(t^2+2t+2), t=e^x
__device__ __forceinline__ float mish_f(float x) {
    if (x > 40.0f) return x;
    float t = __expf(x);
    float u = t * t + 2.0f * t;
    return x * (u / (u + 2.0f));
}

// ---- geometry: CTA 256(M) x 128(N), warp tile 64x64 (4m x 2n), K-chunk 16 ----
#define KC        16
#define NCHUNK    (DMODEL / KC)      // 48
#define TS        24                 // tile row stride (elements)
#define TB        48                 // tile row stride (bytes)
#define A_ROWS    256
#define B_ROWS    128
#define ASZ       (A_ROWS * TB)      // 12288
#define BSZ       (B_ROWS * TB)      // 6144
#define OFF_Ah    0
#define OFF_Al    ASZ                // 12288
#define OFF_B     (2 * ASZ)          // 24576
#define BUF_SZ    (2 * ASZ + BSZ)    // 30720
#define BUF0_OFF  512
#define EPI_LD    132
#define SMEM_BYTES (512 + 128 * EPI_LD * 4)   // 68096 (> 512 + 2*BUF_SZ = 61952)

// ---------------------------------------------------------------------------
// Weight transpose to fp16: src [K=768][N] fp32 -> dst [N][768] fp16.
// ---------------------------------------------------------------------------
__global__ void k_wconv(const float* __restrict__ src, int N, int mode)
{
    __shared__ float tile[32][33];
    int n0 = blockIdx.x * 32, k0 = blockIdx.y * 32;
    int tx = threadIdx.x, ty = threadIdx.y;
#pragma unroll
    for (int i = 0; i < 32; i += 8)
        tile[ty + i][tx] = src[(size_t)(k0 + ty + i) * N + n0 + tx];
    __syncthreads();
    __half* dst;
    if (mode == 0)      dst = g_W1T;
    else if (mode == 1) dst = g_WqkT;
    else                dst = g_WqkT + 64 * DMODEL;
#pragma unroll
    for (int i = 0; i < 32; i += 8) {
        int n = n0 + ty + i, k = k0 + tx;
        dst[(size_t)n * DMODEL + k] = __float2half_rn(tile[tx][ty + i]);
    }
}

// ---- fragments ----
typedef wmma::fragment<wmma::matrix_a, 16, 16, 16, __half, wmma::row_major> FragA;
typedef wmma::fragment<wmma::matrix_b, 16, 16, 16, __half, wmma::col_major> FragB;
typedef wmma::fragment<wmma::accumulator, 16, 16, 16, float> FragC;

// 64x64 warp tile, single K=16 step per chunk, 2-term A split
__device__ __forceinline__ void compute_chunk(const char* buf, int wm, int wn,
                                              FragC c[4][4])
{
    const __half* Ah = (const __half*)(buf + OFF_Ah);
    const __half* Al = (const __half*)(buf + OFF_Al);
    const __half* Bs = (const __half*)(buf + OFF_B);
    FragA ah[4], al[4];
#pragma unroll
    for (int i = 0; i < 4; i++) {
        wmma::load_matrix_sync(ah[i], Ah + (wm * 64 + i * 16) * TS, TS);
        wmma::load_matrix_sync(al[i], Al + (wm * 64 + i * 16) * TS, TS);
    }
#pragma unroll
    for (int j = 0; j < 4; j++) {
        FragB b;
        wmma::load_matrix_sync(b, Bs + (wn * 64 + j * 16) * TS, TS);
        wmma::mma_sync(c[0][j], ah[0], b, c[0][j]);
        wmma::mma_sync(c[1][j], ah[1], b, c[1][j]);
        wmma::mma_sync(c[2][j], ah[2], b, c[2][j]);
        wmma::mma_sync(c[3][j], ah[3], b, c[3][j]);
        wmma::mma_sync(c[0][j], al[0], b, c[0][j]);
        wmma::mma_sync(c[1][j], al[1], b, c[1][j]);
        wmma::mma_sync(c[2][j], al[2], b, c[2][j]);
        wmma::mma_sync(c[3][j], al[3], b, c[3][j]);
    }
}

// convert 16 fp32 (in regs) -> fp16 hi/lo, store 32B each
__device__ __forceinline__ void convert_store_x(char* dst_hi, char* dst_lo,
                                                const float4 v[4])
{
#pragma unroll
    for (int p = 0; p < 2; p++) {
        float4 a = v[2 * p], b = v[2 * p + 1];
        unsigned h0, l0, h1, l1, h2, l2, h3, l3;
        split2(a.x, a.y, h0, l0);
        split2(a.z, a.w, h1, l1);
        split2(b.x, b.y, h2, l2);
        split2(b.z, b.w, h3, l3);
        *(uint4*)(dst_hi + p * 16) = make_uint4(h0, h1, h2, h3);
        *(uint4*)(dst_lo + p * 16) = make_uint4(l0, l1, l2, l3);
    }
}

// ---------------------------------------------------------------------------
// Kernel A: H = mish(X @ W1 + b1) -> g_Hhi/g_Hlo.
// grid (6, 512), 256 thr, CTA tile 256x128, 1 CTA/SM.
// ---------------------------------------------------------------------------
__global__ __launch_bounds__(256, 1) void k_gemmA(const float* __restrict__ X,
                                                  const float* __restrict__ b1)
{
    extern __shared__ char smem[];
    const unsigned sb = s2u(smem);
    float* bias = (float*)smem;
    const int tid = threadIdx.x, wid = tid >> 5;
    const int wm = wid >> 1, wn = wid & 1;
    const int n0 = blockIdx.x * 128, m0 = blockIdx.y * 256;
    const int r = tid >> 1, half = tid & 1;

    if (tid < 128) bias[tid] = b1[n0 + tid];

    FragC c[4][4];
#pragma unroll
    for (int i = 0; i < 4; i++)
#pragma unroll
        for (int j = 0; j < 4; j++) wmma::fill_fragment(c[i][j], 0.0f);

    const float*  xrow = X + (size_t)(m0 + tid) * DMODEL;     // one 256-row tile, row = tid
    const __half* wr   = g_W1T + (size_t)(n0 + r) * DMODEL + half * 8;
    const unsigned wdst = OFF_B  + r * TB + half * 16;
    const unsigned adh  = OFF_Ah + tid * TB;
    const unsigned adl  = OFF_Al + tid * TB;

    // prologue: chunk 0
    {
        float4 xv[4];
        const float4* xp = (const float4*)xrow;
#pragma unroll
        for (int p = 0; p < 4; p++) xv[p] = xp[p];
        cp16(sb + BUF0_OFF + wdst, wr);
        CP_COMMIT();
        convert_store_x(smem + BUF0_OFF + adh, smem + BUF0_OFF + adl, xv);
        CP_WAIT0();
    }
    __syncthreads();

    for (int ch = 0; ch < NCHUNK; ch++) {
        const int cur = ch & 1;
        char* curbuf = smem + BUF0_OFF + cur * BUF_SZ;
        char* nxtbuf = smem + BUF0_OFF + (1 - cur) * BUF_SZ;
        const unsigned nxtu = sb + BUF0_OFF + (1 - cur) * BUF_SZ;

        float4 xv[4];
        if (ch < NCHUNK - 1) {
            const int k0 = (ch + 1) * KC;
            const float4* xp = (const float4*)(xrow + k0);
#pragma unroll
            for (int p = 0; p < 4; p++) xv[p] = xp[p];
            cp16(nxtu + wdst, wr + k0);
            CP_COMMIT();
        }

        compute_chunk(curbuf, wm, wn, c);

        if (ch < NCHUNK - 1) {
            convert_store_x(nxtbuf + adh, nxtbuf + adl, xv);
            CP_WAIT0();
        }
        __syncthreads();
    }

    // epilogue: two passes of 128 rows x 128 cols
    float* Cs = (float*)(smem + BUF0_OFF);
#pragma unroll
    for (int p = 0; p < 2; p++) {
#pragma unroll
        for (int ii = 0; ii < 2; ii++)
#pragma unroll
            for (int j = 0; j < 4; j++)
                wmma::store_matrix_sync(Cs + (wm * 32 + ii * 16) * EPI_LD + wn * 64 + j * 16,
                                        c[2 * p + ii][j], EPI_LD, wmma::mem_row_major);
        __syncthreads();

        const int grow = m0 + ((r >> 5) * 64) + p * 32 + (r & 31);
        const float* crow = Cs + r * EPI_LD + half * 64;
        const float* bptr = bias + half * 64;
        __half* dh = g_Hhi + (size_t)grow * DMODEL + n0 + half * 64;
        __half* dl = g_Hlo + (size_t)grow * DMODEL + n0 + half * 64;
#pragma unroll
        for (int blk = 0; blk < 8; blk++) {
            unsigned hw[4], lw[4];
#pragma unroll
            for (int e = 0; e < 4; e++) {
                float v0 = mish_f(crow[blk * 8 + 2 * e]     + bptr[blk * 8 + 2 * e]);
                float v1 = mish_f(crow[blk * 8 + 2 * e + 1] + bptr[blk * 8 + 2 * e + 1]);
                split2(v0, v1, hw[e], lw[e]);
            }
            *(uint4*)(dh + blk * 8) = make_uint4(hw[0], hw[1], hw[2], hw[3]);
            *(uint4*)(dl + blk * 8) = make_uint4(lw[0], lw[1], lw[2], lw[3]);
        }
        __syncthreads();
    }
}

// ---------------------------------------------------------------------------
// Kernel B: QK = H @ [Wq|Wk] + bias -> g_QK fp32. grid 512, CTA 256x128.
// ---------------------------------------------------------------------------
__global__ __launch_bounds__(256, 1) void k_gemmB(const float* __restrict__ bq,
                                                  const float* __restrict__ bk)
{
    extern __shared__ char smem[];
    const unsigned sb = s2u(smem);
    float* bias = (float*)smem;
    const int tid = threadIdx.x, wid = tid >> 5;
    const int wm = wid >> 1, wn = wid & 1;
    const int m0 = blockIdx.x * 256;
    const int r = tid >> 1, half = tid & 1;

    if (tid < 128) bias[tid] = (tid < 64) ? bq[tid] : bk[tid - 64];

    FragC c[4][4];
#pragma unroll
    for (int i = 0; i < 4; i++)
#pragma unroll
        for (int j = 0; j < 4; j++) wmma::fill_fragment(c[i][j], 0.0f);

    const __half* ahr = g_Hhi + (size_t)(m0 + tid) * DMODEL;
    const __half* alr = g_Hlo + (size_t)(m0 + tid) * DMODEL;
    const __half* wr  = g_WqkT + (size_t)r * DMODEL + half * 8;
    const unsigned wdst = OFF_B  + r * TB + half * 16;
    const unsigned adh  = OFF_Ah + tid * TB;
    const unsigned adl  = OFF_Al + tid * TB;

    // prologue chunk 0
    cp16(sb + BUF0_OFF + adh,      ahr);
    cp16(sb + BUF0_OFF + adh + 16, ahr + 8);
    cp16(sb + BUF0_OFF + adl,      alr);
    cp16(sb + BUF0_OFF + adl + 16, alr + 8);
    cp16(sb + BUF0_OFF + wdst, wr);
    CP_COMMIT();
    CP_WAIT0();
    __syncthreads();

    for (int ch = 0; ch < NCHUNK; ch++) {
        const int cur = ch & 1;
        char* curbuf = smem + BUF0_OFF + cur * BUF_SZ;
        const unsigned nxtu = sb + BUF0_OFF + (1 - cur) * BUF_SZ;

        if (ch < NCHUNK - 1) {
            const int k0 = (ch + 1) * KC;
            cp16(nxtu + adh,      ahr + k0);
            cp16(nxtu + adh + 16, ahr + k0 + 8);
            cp16(nxtu + adl,      alr + k0);
            cp16(nxtu + adl + 16, alr + k0 + 8);
            cp16(nxtu + wdst, wr + k0);
            CP_COMMIT();
        }
        compute_chunk(curbuf, wm, wn, c);
        if (ch < NCHUNK - 1) CP_WAIT0();
        __syncthreads();
    }

    float* Cs = (float*)(smem + BUF0_OFF);
#pragma unroll
    for (int p = 0; p < 2; p++) {
#pragma unroll
        for (int ii = 0; ii < 2; ii++)
#pragma unroll
            for (int j = 0; j < 4; j++)
                wmma::store_matrix_sync(Cs + (wm * 32 + ii * 16) * EPI_LD + wn * 64 + j * 16,
                                        c[2 * p + ii][j], EPI_LD, wmma::mem_row_major);
        __syncthreads();

        const int grow = m0 + ((r >> 5) * 64) + p * 32 + (r & 31);
        const float* crow = Cs + r * EPI_LD + half * 64;
        const float* bptr = bias + half * 64;
        float* orow = g_QK + (size_t)grow * 128 + half * 64;
#pragma unroll
        for (int blk = 0; blk < 16; blk++) {
            float4 o;
            o.x = crow[blk * 4 + 0] + bptr[blk * 4 + 0];
            o.y = crow[blk * 4 + 1] + bptr[blk * 4 + 1];
            o.z = crow[blk * 4 + 2] + bptr[blk * 4 + 2];
            o.w = crow[blk * 4 + 3] + bptr[blk * 4 + 3];
            *(float4*)(orow + blk * 4) = o;
        }
        __syncthreads();
    }
}

// ---------------------------------------------------------------------------
// Kernel C: per-batch scores (4x4 register tiles) + promotion + gather.
// ---------------------------------------------------------------------------
__global__ __launch_bounds__(256) void k_scores_gather(
    const float* __restrict__ Wp, const float* __restrict__ bp,
    const int* __restrict__ indices, float* __restrict__ out)
{
    __shared__ float q_s[64][65];
    __shared__ float k_s[64][65];
    __shared__ float s_s[64][64];
    __shared__ float prom2[24];

    const int b = blockIdx.x, tid = threadIdx.x;
    for (int i = tid; i < 64 * 64; i += 256) {
        int rr = i >> 6, cc = i & 63;
        const float* row = &g_QK[((size_t)b * 64 + rr) * 128];
        q_s[rr][cc] = row[cc];
        k_s[rr][cc] = row[64 + cc];
    }
    __syncthreads();

    {
        const int tx = tid & 15, ty = tid >> 4;
        const int i0 = ty * 4, j0 = tx * 4;
        float acc[4][4] = {};
#pragma unroll 16
        for (int d = 0; d < 64; d++) {
            float qv[4], kv[4];
#pragma unroll
            for (int a = 0; a < 4; a++) { qv[a] = q_s[i0 + a][d]; kv[a] = k_s[j0 + a][d]; }
#pragma unroll
            for (int a = 0; a < 4; a++)
#pragma unroll
                for (int e = 0; e < 4; e++) acc[a][e] += qv[a] * kv[e];
        }
#pragma unroll
        for (int a = 0; a < 4; a++)
#pragma unroll
            for (int e = 0; e < 4; e++) s_s[i0 + a][j0 + e] = acc[a][e] * 0.125f;
    }

    if (tid < 24) {
        int jr = 56 + tid / 3, cc = tid % 3;
        float acc = bp[cc] + bp[3];
#pragma unroll
        for (int d = 0; d < 64; d++)
            acc += k_s[jr][d] * (Wp[d * 4 + cc] + Wp[d * 4 + 3]);
        prom2[tid] = acc;
    }
    __syncthreads();

    for (int t = tid; t < 1858; t += 256) {
        int id = indices[t];
        float v;
        if (id < 4096) v = s_s[id >> 6][id & 63];
        else {
            int p = id - 4096, i = p / 3;
            v = s_s[48 + (i >> 3)][56 + (i & 7)] + prom2[p % 24];
        }
        out[(size_t)b * 1858 + t] = v;
    }
}

// ---------------------------------------------------------------------------
extern "C" void kernel_launch(void* const* d_in, const int* in_sizes, int n_in,
                              void* d_out, int out_size)
{
    const float* x  = (const float*)d_in[0];
    const float* W1 = (const float*)d_in[1];
    const float* b1 = (const float*)d_in[2];
    const float* Wq = (const float*)d_in[3];
    const float* bq = (const float*)d_in[4];
    const float* Wk = (const float*)d_in[5];
    const float* bk = (const float*)d_in[6];
    const float* Wp = (const float*)d_in[7];
    const float* bp = (const float*)d_in[8];
    const int*  idx = (const int*)d_in[9];

    cudaFuncSetAttribute(k_gemmA, cudaFuncAttributeMaxDynamicSharedMemorySize, SMEM_BYTES);
    cudaFuncSetAttribute(k_gemmB, cudaFuncAttributeMaxDynamicSharedMemorySize, SMEM_BYTES);

    k_wconv<<<dim3(24, 24), dim3(32, 8)>>>(W1, 768, 0);
    k_wconv<<<dim3(2, 24),  dim3(32, 8)>>>(Wq, 64, 1);
    k_wconv<<<dim3(2, 24),  dim3(32, 8)>>>(Wk, 64, 2);

    k_gemmA<<<dim3(6, 512), 256, SMEM_BYTES>>>(x, b1);
    k_gemmB<<<512, 256, SMEM_BYTES>>>(bq, bk);
    k_scores_gather<<<B_BATCH, 256>>>(Wp, bp, idx, (float*)d_out);
}

// round 11
// speedup vs baseline: 1.2918x; 1.2918x over previous
#include <cuda_runtime.h>
#include <cuda_fp16.h>
#include <mma.h>
#include <math.h>

using namespace nvcuda;

#define B_BATCH 2048
#define DMODEL  768
#define M_ROWS  (B_BATCH * 64)   // 131072

__device__ __half g_Hhi[(size_t)M_ROWS * DMODEL];
__device__ __half g_Hlo[(size_t)M_ROWS * DMODEL];
__device__ float  g_QK [(size_t)M_ROWS * 128];
__device__ __half g_W1T [DMODEL * DMODEL];
__device__ __half g_WqkT[128 * DMODEL];

// ---------------- helpers ----------------
__device__ __forceinline__ unsigned s2u(const void* p) {
    unsigned a;
    asm("{ .reg .u64 t; cvta.to.shared.u64 t, %1; cvt.u32.u64 %0, t; }" : "=r"(a) : "l"(p));
    return a;
}
__device__ __forceinline__ void cp16(unsigned dst, const void* src) {
    asm volatile("cp.async.cg.shared.global [%0], [%1], 16;" :: "r"(dst), "l"(src));
}
#define CP_COMMIT() asm volatile("cp.async.commit_group;" ::: "memory")
#define CP_WAIT0()  asm volatile("cp.async.wait_group 0;" ::: "memory")

__device__ __forceinline__ unsigned h2u(__half2 v) { return *reinterpret_cast<unsigned*>(&v); }

// exact fp32 -> fp16 hi+lo split for a pair
__device__ __forceinline__ void split2(float x, float y, unsigned& hi, unsigned& lo) {
    __half2 h = __floats2half2_rn(x, y);
    __half2 l = __floats2half2_rn(x - __low2float(h), y - __high2float(h));
    hi = h2u(h); lo = h2u(l);
}
__device__ __forceinline__ void splitA(float2 v, unsigned& hi, unsigned& lo) {
    split2(v.x, v.y, hi, lo);
}

// mish(x) = x*tanh(softplus(x)) = x*(t^2+2t)/(t^2+2t+2), t=e^x
__device__ __forceinline__ float mish_f(float x) {
    if (x > 40.0f) return x;
    float t = __expf(x);
    float u = t * t + 2.0f * t;
    return x * (u / (u + 2.0f));
}

// raw tensor-core ops
__device__ __forceinline__ void mma_16816(float d[4], const unsigned a[4],
                                          unsigned b0, unsigned b1) {
    asm volatile(
        "mma.sync.aligned.m16n8k16.row.col.f32.f16.f16.f32 "
        "{%0,%1,%2,%3}, {%4,%5,%6,%7}, {%8,%9}, {%0,%1,%2,%3};"
        : "+f"(d[0]), "+f"(d[1]), "+f"(d[2]), "+f"(d[3])
        : "r"(a[0]), "r"(a[1]), "r"(a[2]), "r"(a[3]), "r"(b0), "r"(b1));
}
__device__ __forceinline__ void ldsm4(unsigned r[4], unsigned addr) {
    asm volatile("ldmatrix.sync.aligned.m8n8.x4.shared.b16 {%0,%1,%2,%3}, [%4];"
                 : "=r"(r[0]), "=r"(r[1]), "=r"(r[2]), "=r"(r[3]) : "r"(addr));
}

// ---------------------------------------------------------------------------
// Weight transpose to fp16: src [K=768][N] fp32 -> dst [N][768] fp16.
// ---------------------------------------------------------------------------
__global__ void k_wconv(const float* __restrict__ src, int N, int mode)
{
    __shared__ float tile[32][33];
    int n0 = blockIdx.x * 32, k0 = blockIdx.y * 32;
    int tx = threadIdx.x, ty = threadIdx.y;
#pragma unroll
    for (int i = 0; i < 32; i += 8)
        tile[ty + i][tx] = src[(size_t)(k0 + ty + i) * N + n0 + tx];
    __syncthreads();
    __half* dst;
    if (mode == 0)      dst = g_W1T;
    else if (mode == 1) dst = g_WqkT;
    else                dst = g_WqkT + 64 * DMODEL;
#pragma unroll
    for (int i = 0; i < 32; i += 8) {
        int n = n0 + ty + i, k = k0 + tx;
        dst[(size_t)n * DMODEL + k] = __float2half_rn(tile[tx][ty + i]);
    }
}

#define EPI_LD 132
#define SMEM_BYTES (512 + 128 * EPI_LD * 4)   // 68096

// ---------------------------------------------------------------------------
// Kernel A (raw mma.sync): H = mish(X @ W1 + b1) -> g_Hhi/g_Hlo.
// CTA 128x128, 8 warps (4m x 2n), warp tile 32x64, KC=64 (12 chunks).
// A operand: LDG fp32 direct -> in-register fp16 hi/lo split (no smem for X).
// W operand: cp.async into XOR-swizzled smem (128B rows), ldmatrix.x4.
// grid (6, 1024), 256 thr, 2 CTAs/SM target.
// ---------------------------------------------------------------------------
#define AKC 64
#define ANCH (DMODEL / AKC)     // 12
#define WBUF_SZ 16384           // 128 rows x 128B

__global__ __launch_bounds__(256, 2) void k_gemmA(const float* __restrict__ X,
                                                  const float* __restrict__ b1)
{
    extern __shared__ char smem[];
    const unsigned sb = s2u(smem);
    float* bias = (float*)smem;
    const int tid = threadIdx.x, wid = tid >> 5, lane = tid & 31;
    const int wm = wid & 3, wn = wid >> 2;           // 4m x 2n
    const int n0 = blockIdx.x * 128, m0 = blockIdx.y * 128;
    const int g  = lane >> 2, cq = lane & 3;
    const int seg = lane >> 4, x7 = lane & 7;

    if (tid < 128) bias[tid] = b1[n0 + tid];

    float acc[2][8][4];
#pragma unroll
    for (int t = 0; t < 2; t++)
#pragma unroll
        for (int j = 0; j < 8; j++)
#pragma unroll
            for (int e = 0; e < 4; e++) acc[t][j][e] = 0.0f;

    // A: direct-LDG pointer (fragment layout: rows g,g+8 / cols cq*2, cq*2+8)
    const float* pA = X + (size_t)(m0 + wm * 32 + g) * DMODEL + cq * 2;

    // W staging: thread (r = tid>>1, h = tid&1) writes 4 x 16B, swizzled
    const int r = tid >> 1, h = tid & 1;
    const __half* wsrc = g_W1T + (size_t)(n0 + r) * DMODEL + h * 32;
    unsigned wdoff[4];
#pragma unroll
    for (int s = 0; s < 4; s++)
        wdoff[s] = (unsigned)(r * 128 + ((((h << 2) + s) ^ (r & 7)) << 4));

    // ldmatrix row offsets: 4 groups of n16 (i = bt*2+q), rows = lane&15
    unsigned rowoff[4];
#pragma unroll
    for (int i = 0; i < 4; i++)
        rowoff[i] = (unsigned)((wn * 64 + i * 16 + (lane & 15)) * 128);

    const unsigned WB0 = sb + 512, WB1 = sb + 512 + WBUF_SZ;

    // prologue: stage W chunk 0
#pragma unroll
    for (int s = 0; s < 4; s++) cp16(WB0 + wdoff[s], wsrc + s * 8);
    CP_COMMIT();
    CP_WAIT0();
    __syncthreads();

    for (int ch = 0; ch < ANCH; ch++) {
        const unsigned sw  = (ch & 1) ? WB1 : WB0;
        const unsigned nxt = (ch & 1) ? WB0 : WB1;

        if (ch < ANCH - 1) {
            const int k0 = (ch + 1) * AKC;
#pragma unroll
            for (int s = 0; s < 4; s++) cp16(nxt + wdoff[s], wsrc + k0 + s * 8);
            CP_COMMIT();
        }

#pragma unroll
        for (int ks = 0; ks < 4; ks++) {
            const int k = ch * AKC + ks * 16;
            // A fragments: LDG + split in registers
            unsigned ahi[2][4], alo[2][4];
#pragma unroll
            for (int t = 0; t < 2; t++) {
                const float* p = pA + (size_t)t * 16 * DMODEL + k;
                float2 v0 = *(const float2*)p;
                float2 v1 = *(const float2*)(p + 8 * DMODEL);
                float2 v2 = *(const float2*)(p + 8);
                float2 v3 = *(const float2*)(p + 8 * DMODEL + 8);
                splitA(v0, ahi[t][0], alo[t][0]);
                splitA(v1, ahi[t][1], alo[t][1]);
                splitA(v2, ahi[t][2], alo[t][2]);
                splitA(v3, ahi[t][3], alo[t][3]);
            }
            // B fragments from swizzled smem + MMAs (2 batches of n32)
#pragma unroll
            for (int bt = 0; bt < 2; bt++) {
                unsigned br[2][4];
#pragma unroll
                for (int q = 0; q < 2; q++) {
                    unsigned unit = (unsigned)(((ks << 1) + seg) ^ x7);
                    ldsm4(br[q], sw + rowoff[bt * 2 + q] + (unit << 4));
                }
#pragma unroll
                for (int q = 0; q < 2; q++)
#pragma unroll
                    for (int s = 0; s < 2; s++) {
                        const int j = bt * 4 + q * 2 + s;
                        mma_16816(acc[0][j], ahi[0], br[q][s], br[q][s + 2]);
                        mma_16816(acc[1][j], ahi[1], br[q][s], br[q][s + 2]);
                        mma_16816(acc[0][j], alo[0], br[q][s], br[q][s + 2]);
                        mma_16816(acc[1][j], alo[1], br[q][s], br[q][s + 2]);
                    }
            }
        }

        if (ch < ANCH - 1) CP_WAIT0();
        __syncthreads();
    }

    // epilogue: regs -> smem (fp32), then bias+mish+split -> gmem (R9 tail)
    float* Cs = (float*)(smem + 512);
#pragma unroll
    for (int t = 0; t < 2; t++)
#pragma unroll
        for (int j = 0; j < 8; j++) {
            const int row = wm * 32 + t * 16 + g;
            const int col = wn * 64 + j * 8 + cq * 2;
            Cs[row * EPI_LD + col]           = acc[t][j][0];
            Cs[row * EPI_LD + col + 1]       = acc[t][j][1];
            Cs[(row + 8) * EPI_LD + col]     = acc[t][j][2];
            Cs[(row + 8) * EPI_LD + col + 1] = acc[t][j][3];
        }
    __syncthreads();

    const float* crow = Cs + r * EPI_LD + h * 64;
    const float* bptr = bias + h * 64;
    __half* dh = g_Hhi + (size_t)(m0 + r) * DMODEL + n0 + h * 64;
    __half* dl = g_Hlo + (size_t)(m0 + r) * DMODEL + n0 + h * 64;
#pragma unroll
    for (int blk = 0; blk < 8; blk++) {
        unsigned hw[4], lw[4];
#pragma unroll
        for (int e = 0; e < 4; e++) {
            float v0 = mish_f(crow[blk * 8 + 2 * e]     + bptr[blk * 8 + 2 * e]);
            float v1 = mish_f(crow[blk * 8 + 2 * e + 1] + bptr[blk * 8 + 2 * e + 1]);
            split2(v0, v1, hw[e], lw[e]);
        }
        *(uint4*)(dh + blk * 8) = make_uint4(hw[0], hw[1], hw[2], hw[3]);
        *(uint4*)(dl + blk * 8) = make_uint4(lw[0], lw[1], lw[2], lw[3]);
    }
}

// ---------------------------------------------------------------------------
// Kernel B (wmma, unchanged from R9): QK = H @ [Wq|Wk] + bias -> g_QK fp32.
// ---------------------------------------------------------------------------
#define KC        32
#define NCHUNK    (DMODEL / KC)      // 24
#define TS        40
#define TB        80
#define TILE_SZ   10240
#define OFF_Ah    0
#define OFF_Al    TILE_SZ
#define OFF_B     (2 * TILE_SZ)
#define BUF_SZ    (3 * TILE_SZ)
#define BUF0_OFF  512

typedef wmma::fragment<wmma::matrix_a, 16, 16, 16, __half, wmma::row_major> FragA;
typedef wmma::fragment<wmma::matrix_b, 16, 16, 16, __half, wmma::col_major> FragB;
typedef wmma::fragment<wmma::accumulator, 16, 16, 16, float> FragC;

__device__ __forceinline__ void compute_chunkB(const char* buf, int wm, int wn,
                                               FragC c[2][4])
{
    const __half* Ah = (const __half*)(buf + OFF_Ah);
    const __half* Al = (const __half*)(buf + OFF_Al);
    const __half* Bs = (const __half*)(buf + OFF_B);
#pragma unroll
    for (int ks = 0; ks < 2; ks++) {
        FragA ah[2], al[2];
#pragma unroll
        for (int i = 0; i < 2; i++) {
            wmma::load_matrix_sync(ah[i], Ah + (wm * 32 + i * 16) * TS + ks * 16, TS);
            wmma::load_matrix_sync(al[i], Al + (wm * 32 + i * 16) * TS + ks * 16, TS);
        }
#pragma unroll
        for (int j = 0; j < 4; j++) {
            FragB b;
            wmma::load_matrix_sync(b, Bs + (wn * 64 + j * 16) * TS + ks * 16, TS);
            wmma::mma_sync(c[0][j], ah[0], b, c[0][j]);
            wmma::mma_sync(c[1][j], ah[1], b, c[1][j]);
            wmma::mma_sync(c[0][j], al[0], b, c[0][j]);
            wmma::mma_sync(c[1][j], al[1], b, c[1][j]);
        }
    }
}

__device__ __forceinline__ void stage_row32(unsigned dst, const __half* __restrict__ s)
{
    cp16(dst, s);
    cp16(dst + 16, s + 8);
}

__global__ __launch_bounds__(256, 2) void k_gemmB(const float* __restrict__ bq,
                                                  const float* __restrict__ bk)
{
    extern __shared__ char smem[];
    const unsigned sb = s2u(smem);
    float* bias = (float*)smem;
    const int tid = threadIdx.x, wid = tid >> 5;
    const int wm = wid & 3, wn = wid >> 2;
    const int m0 = blockIdx.x * 128;
    const int r = tid >> 1, half = tid & 1;

    if (tid < 128) bias[tid] = (tid < 64) ? bq[tid] : bk[tid - 64];

    FragC c[2][4];
#pragma unroll
    for (int i = 0; i < 2; i++)
#pragma unroll
        for (int j = 0; j < 4; j++) wmma::fill_fragment(c[i][j], 0.0f);

    const __half* ahr = g_Hhi + (size_t)(m0 + r) * DMODEL + half * 16;
    const __half* alr = g_Hlo + (size_t)(m0 + r) * DMODEL + half * 16;
    const __half* wr  = g_WqkT + (size_t)r * DMODEL + half * 16;
    const unsigned arow = r * TB + half * 32;

    stage_row32(sb + BUF0_OFF + OFF_Ah + arow, ahr);
    stage_row32(sb + BUF0_OFF + OFF_Al + arow, alr);
    stage_row32(sb + BUF0_OFF + OFF_B  + arow, wr);
    CP_COMMIT();
    CP_WAIT0();
    __syncthreads();

    for (int ch = 0; ch < NCHUNK; ch++) {
        const int cur = ch & 1;
        char* curbuf = smem + BUF0_OFF + cur * BUF_SZ;
        const unsigned nxtu = sb + BUF0_OFF + (1 - cur) * BUF_SZ;

        if (ch < NCHUNK - 1) {
            const int k0 = (ch + 1) * KC;
            stage_row32(nxtu + OFF_Ah + arow, ahr + k0);
            stage_row32(nxtu + OFF_Al + arow, alr + k0);
            stage_row32(nxtu + OFF_B  + arow, wr + k0);
            CP_COMMIT();
        }
        compute_chunkB(curbuf, wm, wn, c);
        if (ch < NCHUNK - 1) CP_WAIT0();
        __syncthreads();
    }

    float* Cs = (float*)(smem + BUF0_OFF);
#pragma unroll
    for (int i = 0; i < 2; i++)
#pragma unroll
        for (int j = 0; j < 4; j++)
            wmma::store_matrix_sync(Cs + (wm * 32 + i * 16) * EPI_LD + wn * 64 + j * 16,
                                    c[i][j], EPI_LD, wmma::mem_row_major);
    __syncthreads();

    const float* crow = Cs + r * EPI_LD + half * 64;
    const float* bptr = bias + half * 64;
    float* orow = g_QK + (size_t)(m0 + r) * 128 + half * 64;
#pragma unroll
    for (int blk = 0; blk < 16; blk++) {
        float4 o;
        o.x = crow[blk * 4 + 0] + bptr[blk * 4 + 0];
        o.y = crow[blk * 4 + 1] + bptr[blk * 4 + 1];
        o.z = crow[blk * 4 + 2] + bptr[blk * 4 + 2];
        o.w = crow[blk * 4 + 3] + bptr[blk * 4 + 3];
        *(float4*)(orow + blk * 4) = o;
    }
}

// ---------------------------------------------------------------------------
// Kernel C: per-batch scores (4x4 register tiles) + promotion + gather.
// ---------------------------------------------------------------------------
__global__ __launch_bounds__(256) void k_scores_gather(
    const float* __restrict__ Wp, const float* __restrict__ bp,
    const int* __restrict__ indices, float* __restrict__ out)
{
    __shared__ float q_s[64][65];
    __shared__ float k_s[64][65];
    __shared__ float s_s[64][64];
    __shared__ float prom2[24];

    const int b = blockIdx.x, tid = threadIdx.x;
    for (int i = tid; i < 64 * 64; i += 256) {
        int rr = i >> 6, cc = i & 63;
        const float* row = &g_QK[((size_t)b * 64 + rr) * 128];
        q_s[rr][cc] = row[cc];
        k_s[rr][cc] = row[64 + cc];
    }
    __syncthreads();

    {
        const int tx = tid & 15, ty = tid >> 4;
        const int i0 = ty * 4, j0 = tx * 4;
        float acc[4][4] = {};
#pragma unroll 16
        for (int d = 0; d < 64; d++) {
            float qv[4], kv[4];
#pragma unroll
            for (int a = 0; a < 4; a++) { qv[a] = q_s[i0 + a][d]; kv[a] = k_s[j0 + a][d]; }
#pragma unroll
            for (int a = 0; a < 4; a++)
#pragma unroll
                for (int e = 0; e < 4; e++) acc[a][e] += qv[a] * kv[e];
        }
#pragma unroll
        for (int a = 0; a < 4; a++)
#pragma unroll
            for (int e = 0; e < 4; e++) s_s[i0 + a][j0 + e] = acc[a][e] * 0.125f;
    }

    if (tid < 24) {
        int jr = 56 + tid / 3, cc = tid % 3;
        float acc = bp[cc] + bp[3];
#pragma unroll
        for (int d = 0; d < 64; d++)
            acc += k_s[jr][d] * (Wp[d * 4 + cc] + Wp[d * 4 + 3]);
        prom2[tid] = acc;
    }
    __syncthreads();

    for (int t = tid; t < 1858; t += 256) {
        int id = indices[t];
        float v;
        if (id < 4096) v = s_s[id >> 6][id & 63];
        else {
            int p = id - 4096, i = p / 3;
            v = s_s[48 + (i >> 3)][56 + (i & 7)] + prom2[p % 24];
        }
        out[(size_t)b * 1858 + t] = v;
    }
}

// ---------------------------------------------------------------------------
extern "C" void kernel_launch(void* const* d_in, const int* in_sizes, int n_in,
                              void* d_out, int out_size)
{
    const float* x  = (const float*)d_in[0];
    const float* W1 = (const float*)d_in[1];
    const float* b1 = (const float*)d_in[2];
    const float* Wq = (const float*)d_in[3];
    const float* bq = (const float*)d_in[4];
    const float* Wk = (const float*)d_in[5];
    const float* bk = (const float*)d_in[6];
    const float* Wp = (const float*)d_in[7];
    const float* bp = (const float*)d_in[8];
    const int*  idx = (const int*)d_in[9];

    cudaFuncSetAttribute(k_gemmA, cudaFuncAttributeMaxDynamicSharedMemorySize, SMEM_BYTES);
    cudaFuncSetAttribute(k_gemmB, cudaFuncAttributeMaxDynamicSharedMemorySize, SMEM_BYTES);

    k_wconv<<<dim3(24, 24), dim3(32, 8)>>>(W1, 768, 0);
    k_wconv<<<dim3(2, 24),  dim3(32, 8)>>>(Wq, 64, 1);
    k_wconv<<<dim3(2, 24),  dim3(32, 8)>>>(Wk, 64, 2);

    k_gemmA<<<dim3(6, 1024), 256, SMEM_BYTES>>>(x, b1);
    k_gemmB<<<1024, 256, SMEM_BYTES>>>(bq, bk);
    k_scores_gather<<<B_BATCH, 256>>>(Wp, bp, idx, (float*)d_out);
}

// round 12
// speedup vs baseline: 1.8232x; 1.4114x over previous
#include <cuda_runtime.h>
#include <cuda_fp16.h>
#include <mma.h>
#include <math.h>

using namespace nvcuda;

#define B_BATCH 2048
#define DMODEL  768
#define M_ROWS  (B_BATCH * 64)   // 131072

__device__ __half g_H  [(size_t)M_ROWS * DMODEL];
__device__ float  g_QK [(size_t)M_ROWS * 128];
__device__ __half g_W1T [DMODEL * DMODEL];
__device__ __half g_WqkT[128 * DMODEL];

// ---------------- helpers ----------------
__device__ __forceinline__ unsigned s2u(const void* p) {
    unsigned a;
    asm("{ .reg .u64 t; cvta.to.shared.u64 t, %1; cvt.u32.u64 %0, t; }" : "=r"(a) : "l"(p));
    return a;
}
__device__ __forceinline__ void cp16(unsigned dst, const void* src) {
    asm volatile("cp.async.cg.shared.global [%0], [%1], 16;" :: "r"(dst), "l"(src));
}
#define CP_COMMIT() asm volatile("cp.async.commit_group;" ::: "memory")
#define CP_WAIT0()  asm volatile("cp.async.wait_group 0;" ::: "memory")

__device__ __forceinline__ unsigned h2u(__half2 v) { return *reinterpret_cast<unsigned*>(&v); }

// mish(x) = x*tanh(softplus(x)) = x*(t^2+2t)/(t^2+2t+2), t=e^x
__device__ __forceinline__ float mish_f(float x) {
    if (x > 40.0f) return x;
    float t = __expf(x);
    float u = t * t + 2.0f * t;
    return x * (u / (u + 2.0f));
}

// ---- geometry (R9-proven): CTA 128x128, K-chunk 32, warp tile 32x64 ----
#define KC        32
#define NCHUNK    (DMODEL / KC)      // 24
#define TS        40                 // tile row stride (elements)
#define TB        80                 // tile row stride (bytes)
#define TILE_SZ   10240              // 128 rows x 80B
#define OFF_A     0
#define OFF_B     TILE_SZ
#define BUF_SZ    (2 * TILE_SZ)      // 20480
#define BUF0_OFF  512
#define EPI_LD    132
#define SMEM_BYTES (512 + 128 * EPI_LD * 4)   // 68096 (> 512 + 2*BUF_SZ = 41472)

// ---------------------------------------------------------------------------
// Weight transpose to fp16: src [K=768][N] fp32 -> dst [N][768] fp16.
// ---------------------------------------------------------------------------
__global__ void k_wconv(const float* __restrict__ src, int N, int mode)
{
    __shared__ float tile[32][33];
    int n0 = blockIdx.x * 32, k0 = blockIdx.y * 32;
    int tx = threadIdx.x, ty = threadIdx.y;
#pragma unroll
    for (int i = 0; i < 32; i += 8)
        tile[ty + i][tx] = src[(size_t)(k0 + ty + i) * N + n0 + tx];
    __syncthreads();
    __half* dst;
    if (mode == 0)      dst = g_W1T;
    else if (mode == 1) dst = g_WqkT;
    else                dst = g_WqkT + 64 * DMODEL;
#pragma unroll
    for (int i = 0; i < 32; i += 8) {
        int n = n0 + ty + i, k = k0 + tx;
        dst[(size_t)n * DMODEL + k] = __float2half_rn(tile[tx][ty + i]);
    }
}

// ---- fragments ----
typedef wmma::fragment<wmma::matrix_a, 16, 16, 16, __half, wmma::row_major> FragA;
typedef wmma::fragment<wmma::matrix_b, 16, 16, 16, __half, wmma::col_major> FragB;
typedef wmma::fragment<wmma::accumulator, 16, 16, 16, float> FragC;

// 32x64 warp tile, single-pass fp16
__device__ __forceinline__ void compute_chunk(const char* buf, int wm, int wn,
                                              FragC c[2][4])
{
    const __half* As = (const __half*)(buf + OFF_A);
    const __half* Bs = (const __half*)(buf + OFF_B);
#pragma unroll
    for (int ks = 0; ks < 2; ks++) {
        FragA a[2];
#pragma unroll
        for (int i = 0; i < 2; i++)
            wmma::load_matrix_sync(a[i], As + (wm * 32 + i * 16) * TS + ks * 16, TS);
#pragma unroll
        for (int j = 0; j < 4; j++) {
            FragB b;
            wmma::load_matrix_sync(b, Bs + (wn * 64 + j * 16) * TS + ks * 16, TS);
            wmma::mma_sync(c[0][j], a[0], b, c[0][j]);
            wmma::mma_sync(c[1][j], a[1], b, c[1][j]);
        }
    }
}

// stage 16 fp16 (32B) of one row via cp.async
__device__ __forceinline__ void stage_row32(unsigned dst, const __half* __restrict__ s)
{
    cp16(dst, s);
    cp16(dst + 16, s + 8);
}

// convert 16 fp32 (in regs) -> fp16, store 32B
__device__ __forceinline__ void convert_store_x(char* dst, const float4 v[4])
{
    unsigned w[8];
#pragma unroll
    for (int p = 0; p < 4; p++) {
        w[2 * p]     = h2u(__floats2half2_rn(v[p].x, v[p].y));
        w[2 * p + 1] = h2u(__floats2half2_rn(v[p].z, v[p].w));
    }
    *(uint4*)(dst)      = make_uint4(w[0], w[1], w[2], w[3]);
    *(uint4*)(dst + 16) = make_uint4(w[4], w[5], w[6], w[7]);
}

// ---------------------------------------------------------------------------
// Kernel A: H = mish(X @ W1 + b1) -> g_H (fp16). grid (6,1024), 256 thr.
// ---------------------------------------------------------------------------
__global__ __launch_bounds__(256, 2) void k_gemmA(const float* __restrict__ X,
                                                  const float* __restrict__ b1)
{
    extern __shared__ char smem[];
    const unsigned sb = s2u(smem);
    float* bias = (float*)smem;
    const int tid = threadIdx.x, wid = tid >> 5;
    const int wm = wid & 3, wn = wid >> 2;
    const int n0 = blockIdx.x * 128, m0 = blockIdx.y * 128;
    const int r = tid >> 1, half = tid & 1;

    if (tid < 128) bias[tid] = b1[n0 + tid];

    FragC c[2][4];
#pragma unroll
    for (int i = 0; i < 2; i++)
#pragma unroll
        for (int j = 0; j < 4; j++) wmma::fill_fragment(c[i][j], 0.0f);

    const float*  xrow = X + (size_t)(m0 + r) * DMODEL + half * 16;
    const __half* wr   = g_W1T + (size_t)(n0 + r) * DMODEL + half * 16;
    const unsigned arow = r * TB + half * 32;

    // prologue: chunk 0
    {
        float4 xv[4];
        const float4* xp = (const float4*)xrow;
#pragma unroll
        for (int p = 0; p < 4; p++) xv[p] = xp[p];
        stage_row32(sb + BUF0_OFF + OFF_B + arow, wr);
        CP_COMMIT();
        convert_store_x(smem + BUF0_OFF + OFF_A + arow, xv);
        CP_WAIT0();
    }
    __syncthreads();

    for (int ch = 0; ch < NCHUNK; ch++) {
        const int cur = ch & 1;
        char* curbuf = smem + BUF0_OFF + cur * BUF_SZ;
        char* nxtbuf = smem + BUF0_OFF + (1 - cur) * BUF_SZ;
        const unsigned nxtu = sb + BUF0_OFF + (1 - cur) * BUF_SZ;

        float4 xv[4];
        if (ch < NCHUNK - 1) {
            const int k0 = (ch + 1) * KC;
            const float4* xp = (const float4*)(xrow + k0);
#pragma unroll
            for (int p = 0; p < 4; p++) xv[p] = xp[p];
            stage_row32(nxtu + OFF_B + arow, wr + k0);
            CP_COMMIT();
        }

        compute_chunk(curbuf, wm, wn, c);

        if (ch < NCHUNK - 1) {
            convert_store_x(nxtbuf + OFF_A + arow, xv);
            CP_WAIT0();
        }
        __syncthreads();
    }

    // epilogue: dump accumulators, bias + mish, store fp16
    float* Cs = (float*)(smem + BUF0_OFF);
#pragma unroll
    for (int i = 0; i < 2; i++)
#pragma unroll
        for (int j = 0; j < 4; j++)
            wmma::store_matrix_sync(Cs + (wm * 32 + i * 16) * EPI_LD + wn * 64 + j * 16,
                                    c[i][j], EPI_LD, wmma::mem_row_major);
    __syncthreads();

    const float* crow = Cs + r * EPI_LD + half * 64;
    const float* bptr = bias + half * 64;
    __half* dh = g_H + (size_t)(m0 + r) * DMODEL + n0 + half * 64;
#pragma unroll
    for (int blk = 0; blk < 8; blk++) {
        unsigned hw[4];
#pragma unroll
        for (int e = 0; e < 4; e++) {
            float v0 = mish_f(crow[blk * 8 + 2 * e]     + bptr[blk * 8 + 2 * e]);
            float v1 = mish_f(crow[blk * 8 + 2 * e + 1] + bptr[blk * 8 + 2 * e + 1]);
            hw[e] = h2u(__floats2half2_rn(v0, v1));
        }
        *(uint4*)(dh + blk * 8) = make_uint4(hw[0], hw[1], hw[2], hw[3]);
    }
}

// ---------------------------------------------------------------------------
// Kernel B: QK = H @ [Wq|Wk] + bias -> g_QK fp32.  grid 1024, 256 thr.
// ---------------------------------------------------------------------------
__global__ __launch_bounds__(256, 2) void k_gemmB(const float* __restrict__ bq,
                                                  const float* __restrict__ bk)
{
    extern __shared__ char smem[];
    const unsigned sb = s2u(smem);
    float* bias = (float*)smem;
    const int tid = threadIdx.x, wid = tid >> 5;
    const int wm = wid & 3, wn = wid >> 2;
    const int m0 = blockIdx.x * 128;
    const int r = tid >> 1, half = tid & 1;

    if (tid < 128) bias[tid] = (tid < 64) ? bq[tid] : bk[tid - 64];

    FragC c[2][4];
#pragma unroll
    for (int i = 0; i < 2; i++)
#pragma unroll
        for (int j = 0; j < 4; j++) wmma::fill_fragment(c[i][j], 0.0f);

    const __half* ahr = g_H + (size_t)(m0 + r) * DMODEL + half * 16;
    const __half* wr  = g_WqkT + (size_t)r * DMODEL + half * 16;
    const unsigned arow = r * TB + half * 32;

    stage_row32(sb + BUF0_OFF + OFF_A + arow, ahr);
    stage_row32(sb + BUF0_OFF + OFF_B + arow, wr);
    CP_COMMIT();
    CP_WAIT0();
    __syncthreads();

    for (int ch = 0; ch < NCHUNK; ch++) {
        const int cur = ch & 1;
        char* curbuf = smem + BUF0_OFF + cur * BUF_SZ;
        const unsigned nxtu = sb + BUF0_OFF + (1 - cur) * BUF_SZ;

        if (ch < NCHUNK - 1) {
            const int k0 = (ch + 1) * KC;
            stage_row32(nxtu + OFF_A + arow, ahr + k0);
            stage_row32(nxtu + OFF_B + arow, wr + k0);
            CP_COMMIT();
        }
        compute_chunk(curbuf, wm, wn, c);
        if (ch < NCHUNK - 1) CP_WAIT0();
        __syncthreads();
    }

    float* Cs = (float*)(smem + BUF0_OFF);
#pragma unroll
    for (int i = 0; i < 2; i++)
#pragma unroll
        for (int j = 0; j < 4; j++)
            wmma::store_matrix_sync(Cs + (wm * 32 + i * 16) * EPI_LD + wn * 64 + j * 16,
                                    c[i][j], EPI_LD, wmma::mem_row_major);
    __syncthreads();

    const float* crow = Cs + r * EPI_LD + half * 64;
    const float* bptr = bias + half * 64;
    float* orow = g_QK + (size_t)(m0 + r) * 128 + half * 64;
#pragma unroll
    for (int blk = 0; blk < 16; blk++) {
        float4 o;
        o.x = crow[blk * 4 + 0] + bptr[blk * 4 + 0];
        o.y = crow[blk * 4 + 1] + bptr[blk * 4 + 1];
        o.z = crow[blk * 4 + 2] + bptr[blk * 4 + 2];
        o.w = crow[blk * 4 + 3] + bptr[blk * 4 + 3];
        *(float4*)(orow + blk * 4) = o;
    }
}

// ---------------------------------------------------------------------------
// Kernel C: per-batch scores (4x4 register tiles) + promotion + gather.
// ---------------------------------------------------------------------------
__global__ __launch_bounds__(256) void k_scores_gather(
    const float* __restrict__ Wp, const float* __restrict__ bp,
    const int* __restrict__ indices, float* __restrict__ out)
{
    __shared__ float q_s[64][65];
    __shared__ float k_s[64][65];
    __shared__ float s_s[64][64];
    __shared__ float prom2[24];

    const int b = blockIdx.x, tid = threadIdx.x;
    for (int i = tid; i < 64 * 64; i += 256) {
        int rr = i >> 6, cc = i & 63;
        const float* row = &g_QK[((size_t)b * 64 + rr) * 128];
        q_s[rr][cc] = row[cc];
        k_s[rr][cc] = row[64 + cc];
    }
    __syncthreads();

    {
        const int tx = tid & 15, ty = tid >> 4;
        const int i0 = ty * 4, j0 = tx * 4;
        float acc[4][4] = {};
#pragma unroll 16
        for (int d = 0; d < 64; d++) {
            float qv[4], kv[4];
#pragma unroll
            for (int a = 0; a < 4; a++) { qv[a] = q_s[i0 + a][d]; kv[a] = k_s[j0 + a][d]; }
#pragma unroll
            for (int a = 0; a < 4; a++)
#pragma unroll
                for (int e = 0; e < 4; e++) acc[a][e] += qv[a] * kv[e];
        }
#pragma unroll
        for (int a = 0; a < 4; a++)
#pragma unroll
            for (int e = 0; e < 4; e++) s_s[i0 + a][j0 + e] = acc[a][e] * 0.125f;
    }

    if (tid < 24) {
        int jr = 56 + tid / 3, cc = tid % 3;
        float acc = bp[cc] + bp[3];
#pragma unroll
        for (int d = 0; d < 64; d++)
            acc += k_s[jr][d] * (Wp[d * 4 + cc] + Wp[d * 4 + 3]);
        prom2[tid] = acc;
    }
    __syncthreads();

    for (int t = tid; t < 1858; t += 256) {
        int id = indices[t];
        float v;
        if (id < 4096) v = s_s[id >> 6][id & 63];
        else {
            int p = id - 4096, i = p / 3;
            v = s_s[48 + (i >> 3)][56 + (i & 7)] + prom2[p % 24];
        }
        out[(size_t)b * 1858 + t] = v;
    }
}

// ---------------------------------------------------------------------------
extern "C" void kernel_launch(void* const* d_in, const int* in_sizes, int n_in,
                              void* d_out, int out_size)
{
    const float* x  = (const float*)d_in[0];
    const float* W1 = (const float*)d_in[1];
    const float* b1 = (const float*)d_in[2];
    const float* Wq = (const float*)d_in[3];
    const float* bq = (const float*)d_in[4];
    const float* Wk = (const float*)d_in[5];
    const float* bk = (const float*)d_in[6];
    const float* Wp = (const float*)d_in[7];
    const float* bp = (const float*)d_in[8];
    const int*  idx = (const int*)d_in[9];

    cudaFuncSetAttribute(k_gemmA, cudaFuncAttributeMaxDynamicSharedMemorySize, SMEM_BYTES);
    cudaFuncSetAttribute(k_gemmB, cudaFuncAttributeMaxDynamicSharedMemorySize, SMEM_BYTES);

    k_wconv<<<dim3(24, 24), dim3(32, 8)>>>(W1, 768, 0);
    k_wconv<<<dim3(2, 24),  dim3(32, 8)>>>(Wq, 64, 1);
    k_wconv<<<dim3(2, 24),  dim3(32, 8)>>>(Wk, 64, 2);

    k_gemmA<<<dim3(6, 1024), 256, SMEM_BYTES>>>(x, b1);
    k_gemmB<<<1024, 256, SMEM_BYTES>>>(bq, bk);
    k_scores_gather<<<B_BATCH, 256>>>(Wp, bp, idx, (float*)d_out);
}

// round 13
// speedup vs baseline: 1.9483x; 1.0686x over previous
#include <cuda_runtime.h>
#include <cuda_fp16.h>
#include <mma.h>
#include <math.h>

using namespace nvcuda;

#define B_BATCH 2048
#define DMODEL  768
#define M_ROWS  (B_BATCH * 64)   // 131072

__device__ __half g_Xh [(size_t)M_ROWS * DMODEL];
__device__ __half g_H  [(size_t)M_ROWS * DMODEL];
__device__ __half g_W1T [DMODEL * DMODEL];
__device__ __half g_WqkT[128 * DMODEL];

// ---------------- helpers ----------------
__device__ __forceinline__ unsigned s2u(const void* p) {
    unsigned a;
    asm("{ .reg .u64 t; cvta.to.shared.u64 t, %1; cvt.u32.u64 %0, t; }" : "=r"(a) : "l"(p));
    return a;
}
__device__ __forceinline__ void cp16(unsigned dst, const void* src) {
    asm volatile("cp.async.cg.shared.global [%0], [%1], 16;" :: "r"(dst), "l"(src));
}
#define CP_COMMIT() asm volatile("cp.async.commit_group;" ::: "memory")
#define CP_WAIT0()  asm volatile("cp.async.wait_group 0;" ::: "memory")

__device__ __forceinline__ unsigned h2u(__half2 v) { return *reinterpret_cast<unsigned*>(&v); }

// mish(x) = x*tanh(softplus(x)) = x*(t^2+2t)/(t^2+2t+2), t=e^x
__device__ __forceinline__ float mish_f(float x) {
    if (x > 40.0f) return x;
    float t = __expf(x);
    float u = t * t + 2.0f * t;
    return x * (u / (u + 2.0f));
}

// ---- geometry (R12-proven): CTA 128x128, K-chunk 32, warp tile 32x64 ----
#define KC        32
#define NCHUNK    (DMODEL / KC)      // 24
#define TS        40                 // tile row stride (elements)
#define TB        80                 // tile row stride (bytes)
#define TILE_SZ   10240              // 128 rows x 80B
#define OFF_A     0
#define OFF_B     TILE_SZ
#define BUF_SZ    (2 * TILE_SZ)      // 20480
#define BUF0_OFF  512
#define EPI_LD    132
#define SMEM_A    (512 + 128 * EPI_LD * 4)          // 68096
#define SMEM_B    (SMEM_A + 64 * 64 * 4 + 128)      // 84608 (+ scores + prom)

// ---------------------------------------------------------------------------
// X convert: fp32 -> fp16 one pass (hoists the per-chunk rounding; identical rn)
// ---------------------------------------------------------------------------
__global__ __launch_bounds__(256) void k_xsplit(const float* __restrict__ X)
{
    const size_t total = (size_t)M_ROWS * DMODEL;
    size_t i = ((size_t)blockIdx.x * blockDim.x + threadIdx.x) * 8;
    const size_t stride = (size_t)gridDim.x * blockDim.x * 8;
    for (; i < total; i += stride) {
        float4 a = *(const float4*)(X + i);
        float4 b = *(const float4*)(X + i + 4);
        unsigned w0 = h2u(__floats2half2_rn(a.x, a.y));
        unsigned w1 = h2u(__floats2half2_rn(a.z, a.w));
        unsigned w2 = h2u(__floats2half2_rn(b.x, b.y));
        unsigned w3 = h2u(__floats2half2_rn(b.z, b.w));
        *(uint4*)(g_Xh + i) = make_uint4(w0, w1, w2, w3);
    }
}

// ---------------------------------------------------------------------------
// Weight transpose to fp16: src [K=768][N] fp32 -> dst [N][768] fp16.
// ---------------------------------------------------------------------------
__global__ void k_wconv(const float* __restrict__ src, int N, int mode)
{
    __shared__ float tile[32][33];
    int n0 = blockIdx.x * 32, k0 = blockIdx.y * 32;
    int tx = threadIdx.x, ty = threadIdx.y;
#pragma unroll
    for (int i = 0; i < 32; i += 8)
        tile[ty + i][tx] = src[(size_t)(k0 + ty + i) * N + n0 + tx];
    __syncthreads();
    __half* dst;
    if (mode == 0)      dst = g_W1T;
    else if (mode == 1) dst = g_WqkT;
    else                dst = g_WqkT + 64 * DMODEL;
#pragma unroll
    for (int i = 0; i < 32; i += 8) {
        int n = n0 + ty + i, k = k0 + tx;
        dst[(size_t)n * DMODEL + k] = __float2half_rn(tile[tx][ty + i]);
    }
}

// ---- fragments ----
typedef wmma::fragment<wmma::matrix_a, 16, 16, 16, __half, wmma::row_major> FragA;
typedef wmma::fragment<wmma::matrix_b, 16, 16, 16, __half, wmma::col_major> FragB;
typedef wmma::fragment<wmma::accumulator, 16, 16, 16, float> FragC;

// 32x64 warp tile, single-pass fp16
__device__ __forceinline__ void compute_chunk(const char* buf, int wm, int wn,
                                              FragC c[2][4])
{
    const __half* As = (const __half*)(buf + OFF_A);
    const __half* Bs = (const __half*)(buf + OFF_B);
#pragma unroll
    for (int ks = 0; ks < 2; ks++) {
        FragA a[2];
#pragma unroll
        for (int i = 0; i < 2; i++)
            wmma::load_matrix_sync(a[i], As + (wm * 32 + i * 16) * TS + ks * 16, TS);
#pragma unroll
        for (int j = 0; j < 4; j++) {
            FragB b;
            wmma::load_matrix_sync(b, Bs + (wn * 64 + j * 16) * TS + ks * 16, TS);
            wmma::mma_sync(c[0][j], a[0], b, c[0][j]);
            wmma::mma_sync(c[1][j], a[1], b, c[1][j]);
        }
    }
}

__device__ __forceinline__ void stage_row32(unsigned dst, const __half* __restrict__ s)
{
    cp16(dst, s);
    cp16(dst + 16, s + 8);
}

// ---------------------------------------------------------------------------
// Kernel A: H = mish(Xh @ W1 + b1) -> g_H (fp16). grid (6,1024), 256 thr.
// All-cp.async staging (X pre-converted by k_xsplit).
// ---------------------------------------------------------------------------
__global__ __launch_bounds__(256, 2) void k_gemmA(const float* __restrict__ b1)
{
    extern __shared__ char smem[];
    const unsigned sb = s2u(smem);
    float* bias = (float*)smem;
    const int tid = threadIdx.x, wid = tid >> 5;
    const int wm = wid & 3, wn = wid >> 2;
    const int n0 = blockIdx.x * 128, m0 = blockIdx.y * 128;
    const int r = tid >> 1, half = tid & 1;

    if (tid < 128) bias[tid] = b1[n0 + tid];

    FragC c[2][4];
#pragma unroll
    for (int i = 0; i < 2; i++)
#pragma unroll
        for (int j = 0; j < 4; j++) wmma::fill_fragment(c[i][j], 0.0f);

    const __half* ar = g_Xh + (size_t)(m0 + r) * DMODEL + half * 16;
    const __half* wr = g_W1T + (size_t)(n0 + r) * DMODEL + half * 16;
    const unsigned arow = r * TB + half * 32;

    stage_row32(sb + BUF0_OFF + OFF_A + arow, ar);
    stage_row32(sb + BUF0_OFF + OFF_B + arow, wr);
    CP_COMMIT();
    CP_WAIT0();
    __syncthreads();

    for (int ch = 0; ch < NCHUNK; ch++) {
        const int cur = ch & 1;
        char* curbuf = smem + BUF0_OFF + cur * BUF_SZ;
        const unsigned nxtu = sb + BUF0_OFF + (1 - cur) * BUF_SZ;

        if (ch < NCHUNK - 1) {
            const int k0 = (ch + 1) * KC;
            stage_row32(nxtu + OFF_A + arow, ar + k0);
            stage_row32(nxtu + OFF_B + arow, wr + k0);
            CP_COMMIT();
        }
        compute_chunk(curbuf, wm, wn, c);
        if (ch < NCHUNK - 1) CP_WAIT0();
        __syncthreads();
    }

    // epilogue: dump accumulators, bias + mish, store fp16
    float* Cs = (float*)(smem + BUF0_OFF);
#pragma unroll
    for (int i = 0; i < 2; i++)
#pragma unroll
        for (int j = 0; j < 4; j++)
            wmma::store_matrix_sync(Cs + (wm * 32 + i * 16) * EPI_LD + wn * 64 + j * 16,
                                    c[i][j], EPI_LD, wmma::mem_row_major);
    __syncthreads();

    const float* crow = Cs + r * EPI_LD + half * 64;
    const float* bptr = bias + half * 64;
    __half* dh = g_H + (size_t)(m0 + r) * DMODEL + n0 + half * 64;
#pragma unroll
    for (int blk = 0; blk < 8; blk++) {
        unsigned hw[4];
#pragma unroll
        for (int e = 0; e < 4; e++) {
            float v0 = mish_f(crow[blk * 8 + 2 * e]     + bptr[blk * 8 + 2 * e]);
            float v1 = mish_f(crow[blk * 8 + 2 * e + 1] + bptr[blk * 8 + 2 * e + 1]);
            hw[e] = h2u(__floats2half2_rn(v0, v1));
        }
        *(uint4*)(dh + blk * 8) = make_uint4(hw[0], hw[1], hw[2], hw[3]);
    }
}

// ---------------------------------------------------------------------------
// Kernel BC (fused): QK = H @ [Wq|Wk] + bias, then scores + promotion + gather
// for the CTA's 2 batches, straight from smem. grid 1024, 256 thr.
// ---------------------------------------------------------------------------
__global__ __launch_bounds__(256, 2) void k_gemmBC(
    const float* __restrict__ bq, const float* __restrict__ bk,
    const float* __restrict__ Wp, const float* __restrict__ bp,
    const int* __restrict__ indices, float* __restrict__ out)
{
    extern __shared__ char smem[];
    const unsigned sb = s2u(smem);
    float* bias = (float*)smem;
    const int tid = threadIdx.x, wid = tid >> 5;
    const int wm = wid & 3, wn = wid >> 2;
    const int m0 = blockIdx.x * 128;
    const int r = tid >> 1, half = tid & 1;

    if (tid < 128) bias[tid] = (tid < 64) ? bq[tid] : bk[tid - 64];

    FragC c[2][4];
#pragma unroll
    for (int i = 0; i < 2; i++)
#pragma unroll
        for (int j = 0; j < 4; j++) wmma::fill_fragment(c[i][j], 0.0f);

    const __half* ahr = g_H + (size_t)(m0 + r) * DMODEL + half * 16;
    const __half* wr  = g_WqkT + (size_t)r * DMODEL + half * 16;
    const unsigned arow = r * TB + half * 32;

    stage_row32(sb + BUF0_OFF + OFF_A + arow, ahr);
    stage_row32(sb + BUF0_OFF + OFF_B + arow, wr);
    CP_COMMIT();
    CP_WAIT0();
    __syncthreads();

    for (int ch = 0; ch < NCHUNK; ch++) {
        const int cur = ch & 1;
        char* curbuf = smem + BUF0_OFF + cur * BUF_SZ;
        const unsigned nxtu = sb + BUF0_OFF + (1 - cur) * BUF_SZ;

        if (ch < NCHUNK - 1) {
            const int k0 = (ch + 1) * KC;
            stage_row32(nxtu + OFF_A + arow, ahr + k0);
            stage_row32(nxtu + OFF_B + arow, wr + k0);
            CP_COMMIT();
        }
        compute_chunk(curbuf, wm, wn, c);
        if (ch < NCHUNK - 1) CP_WAIT0();
        __syncthreads();
    }

    // dump QK + bias into Cs: row = m-row (0..127), col 0..63 = q, 64..127 = k
    float* Cs = (float*)(smem + BUF0_OFF);
#pragma unroll
    for (int i = 0; i < 2; i++)
#pragma unroll
        for (int j = 0; j < 4; j++)
            wmma::store_matrix_sync(Cs + (wm * 32 + i * 16) * EPI_LD + wn * 64 + j * 16,
                                    c[i][j], EPI_LD, wmma::mem_row_major);
    __syncthreads();
    // add bias in-place (each thread owns one row-half)
    {
        float* crow = Cs + r * EPI_LD + half * 64;
        const float* bptr = bias + half * 64;
#pragma unroll
        for (int e = 0; e < 16; e++) {
            float4 v = *(float4*)(crow + e * 4);
            v.x += bptr[e * 4 + 0]; v.y += bptr[e * 4 + 1];
            v.z += bptr[e * 4 + 2]; v.w += bptr[e * 4 + 3];
            *(float4*)(crow + e * 4) = v;
        }
    }
    __syncthreads();

    // per-batch scores + promotion + gather (2 batches in this CTA)
    float* s_s   = (float*)(smem + SMEM_A);
    float* prom2 = s_s + 64 * 64;
    const int tx = tid & 15, ty = tid >> 4;
    const int i0 = ty * 4, j0 = tx * 4;

    for (int bb = 0; bb < 2; bb++) {
        const float* qs = Cs + bb * 64 * EPI_LD;        // [64][EPI_LD], cols 0..63
        const float* ks = Cs + bb * 64 * EPI_LD + 64;   // cols 64..127

        float acc[4][4] = {};
#pragma unroll 16
        for (int d = 0; d < 64; d++) {
            float qv[4], kv[4];
#pragma unroll
            for (int a = 0; a < 4; a++) { qv[a] = qs[(i0 + a) * EPI_LD + d]; kv[a] = ks[(j0 + a) * EPI_LD + d]; }
#pragma unroll
            for (int a = 0; a < 4; a++)
#pragma unroll
                for (int e = 0; e < 4; e++) acc[a][e] += qv[a] * kv[e];
        }
#pragma unroll
        for (int a = 0; a < 4; a++)
#pragma unroll
            for (int e = 0; e < 4; e++) s_s[(i0 + a) * 64 + j0 + e] = acc[a][e] * 0.125f;

        if (tid < 24) {
            int jr = 56 + tid / 3, cc = tid % 3;
            float pa = bp[cc] + bp[3];
#pragma unroll
            for (int d = 0; d < 64; d++)
                pa += ks[jr * EPI_LD + d] * (Wp[d * 4 + cc] + Wp[d * 4 + 3]);
            prom2[tid] = pa;
        }
        __syncthreads();

        float* orow = out + (size_t)(blockIdx.x * 2 + bb) * 1858;
        for (int t = tid; t < 1858; t += 256) {
            int id = indices[t];
            float v;
            if (id < 4096) v = s_s[(id >> 6) * 64 + (id & 63)];
            else {
                int p = id - 4096, i = p / 3;
                v = s_s[(48 + (i >> 3)) * 64 + 56 + (i & 7)] + prom2[p % 24];
            }
            orow[t] = v;
        }
        __syncthreads();
    }
}

// ---------------------------------------------------------------------------
extern "C" void kernel_launch(void* const* d_in, const int* in_sizes, int n_in,
                              void* d_out, int out_size)
{
    const float* x  = (const float*)d_in[0];
    const float* W1 = (const float*)d_in[1];
    const float* b1 = (const float*)d_in[2];
    const float* Wq = (const float*)d_in[3];
    const float* bq = (const float*)d_in[4];
    const float* Wk = (const float*)d_in[5];
    const float* bk = (const float*)d_in[6];
    const float* Wp = (const float*)d_in[7];
    const float* bp = (const float*)d_in[8];
    const int*  idx = (const int*)d_in[9];

    cudaFuncSetAttribute(k_gemmA,  cudaFuncAttributeMaxDynamicSharedMemorySize, SMEM_A);
    cudaFuncSetAttribute(k_gemmBC, cudaFuncAttributeMaxDynamicSharedMemorySize, SMEM_B);

    k_xsplit<<<4736, 256>>>(x);
    k_wconv<<<dim3(24, 24), dim3(32, 8)>>>(W1, 768, 0);
    k_wconv<<<dim3(2, 24),  dim3(32, 8)>>>(Wq, 64, 1);
    k_wconv<<<dim3(2, 24),  dim3(32, 8)>>>(Wk, 64, 2);

    k_gemmA<<<dim3(6, 1024), 256, SMEM_A>>>(b1);
    k_gemmBC<<<1024, 256, SMEM_B>>>(bq, bk, Wp, bp, idx, (float*)d_out);
}